// round 2
// baseline (speedup 1.0000x reference)
#include <cuda_runtime.h>
#include <math.h>
#include <float.h>

#define B_   2
#define S_   2048
#define E_   2048
#define H_   32
#define KV_  8
#define D_   128
#define NTOK (B_ * S_)

// Scratch (no cudaMalloc allowed): Q, K, V post-projection, and attention context.
__device__ float g_q[(size_t)NTOK * H_ * D_];    // 64 MB  [token][h*128+d]
__device__ float g_k[(size_t)NTOK * KV_ * D_];   // 16 MB  [token][kv*128+d]
__device__ float g_v[(size_t)NTOK * KV_ * D_];   // 16 MB
__device__ float g_ctx[(size_t)NTOK * H_ * D_];  // 64 MB  [token][h*128+d]

// ---------------------------------------------------------------------------
// SGEMM: C[M,N] = A[M,K] @ B[K,N] (+ bias).  BM=BN=128, BK=8, 256 threads,
// 8x8 microtile, software-pipelined global loads (register prefetch).
// M,N multiples of 128; K multiple of 8 (true for all 4 calls).
// ---------------------------------------------------------------------------
__global__ __launch_bounds__(256, 2) void sgemm_bias_kernel(
    const float* __restrict__ A, const float* __restrict__ Bm,
    const float* __restrict__ bias, float* __restrict__ C,
    int M, int N, int K)
{
    __shared__ float As[8][128];
    __shared__ float Bs[8][128];
    const int tid  = threadIdx.x;
    const int bx   = blockIdx.x, by = blockIdx.y;
    const int arow = tid >> 1, acol = (tid & 1) << 2;   // A: 128 rows x 8 k
    const int brow = tid >> 5, bcol = (tid & 31) << 2;  // B: 8 k x 128 cols
    const int trow = (tid >> 4) << 3;                   // 0..120
    const int tcol = (tid & 15) << 3;                   // 0..120

    const float* Ap = A + (size_t)(by * 128 + arow) * K + acol;
    const float* Bp = Bm + (size_t)brow * N + bx * 128 + bcol;

    float acc[8][8];
#pragma unroll
    for (int i = 0; i < 8; i++)
#pragma unroll
        for (int j = 0; j < 8; j++) acc[i][j] = 0.f;

    // Prologue: load first k-tile
    float4 a4 = *(const float4*)(Ap);
    float4 b4 = *(const float4*)(Bp);

    for (int k0 = 0; k0 < K; k0 += 8) {
        // Commit current tile to smem
        As[acol + 0][arow] = a4.x;
        As[acol + 1][arow] = a4.y;
        As[acol + 2][arow] = a4.z;
        As[acol + 3][arow] = a4.w;
        *(float4*)&Bs[brow][bcol] = b4;
        __syncthreads();

        // Prefetch next tile into registers (overlaps with compute below)
        if (k0 + 8 < K) {
            a4 = *(const float4*)(Ap + k0 + 8);
            b4 = *(const float4*)(Bp + (size_t)(k0 + 8) * N);
        }

#pragma unroll
        for (int kk = 0; kk < 8; kk++) {
            float4 a0 = *(const float4*)&As[kk][trow];
            float4 a1 = *(const float4*)&As[kk][trow + 4];
            float4 b0 = *(const float4*)&Bs[kk][tcol];
            float4 b1 = *(const float4*)&Bs[kk][tcol + 4];
            float ra[8] = {a0.x, a0.y, a0.z, a0.w, a1.x, a1.y, a1.z, a1.w};
            float rb[8] = {b0.x, b0.y, b0.z, b0.w, b1.x, b1.y, b1.z, b1.w};
#pragma unroll
            for (int i = 0; i < 8; i++)
#pragma unroll
                for (int j = 0; j < 8; j++)
                    acc[i][j] = fmaf(ra[i], rb[j], acc[i][j]);
        }
        __syncthreads();
    }

    float bb[8];
#pragma unroll
    for (int j = 0; j < 8; j++) bb[j] = bias ? bias[bx * 128 + tcol + j] : 0.f;

#pragma unroll
    for (int i = 0; i < 8; i++) {
        float* cp = C + (size_t)(by * 128 + trow + i) * N + bx * 128 + tcol;
#pragma unroll
        for (int j4 = 0; j4 < 2; j4++) {
            float4 o;
            o.x = acc[i][j4 * 4 + 0] + bb[j4 * 4 + 0];
            o.y = acc[i][j4 * 4 + 1] + bb[j4 * 4 + 1];
            o.z = acc[i][j4 * 4 + 2] + bb[j4 * 4 + 2];
            o.w = acc[i][j4 * 4 + 3] + bb[j4 * 4 + 3];
            ((float4*)cp)[j4] = o;
        }
    }
}

// ---------------------------------------------------------------------------
// Fused RMSNorm (per head, over D=128) + RoPE. One warp per (token, head).
// Lane l holds d = 4l..4l+3; rotate-half partner lives in lane l^16.
// ---------------------------------------------------------------------------
__global__ __launch_bounds__(256) void rmsrope_kernel(
    float* __restrict__ t, const float* __restrict__ cosT,
    const float* __restrict__ sinT, const float* __restrict__ scale, int heads)
{
    int gw   = (blockIdx.x * 256 + threadIdx.x) >> 5;
    int lane = threadIdx.x & 31;
    if (gw >= NTOK * heads) return;
    int token = gw / heads;
    int h     = gw - token * heads;
    int s     = token & (S_ - 1);

    float* row = t + ((size_t)token * heads + h) * D_;
    float4 x = *(const float4*)(row + lane * 4);

    float ss = fmaf(x.x, x.x, fmaf(x.y, x.y, fmaf(x.z, x.z, x.w * x.w)));
#pragma unroll
    for (int o = 16; o; o >>= 1) ss += __shfl_xor_sync(0xffffffffu, ss, o);
    float r = rsqrtf(ss * (1.0f / D_) + 1e-6f);

    float4 sc = *(const float4*)(scale + lane * 4);
    float4 y;
    y.x = x.x * r * sc.x; y.y = x.y * r * sc.y;
    y.z = x.z * r * sc.z; y.w = x.w * r * sc.w;

    float4 p;
    p.x = __shfl_xor_sync(0xffffffffu, y.x, 16);
    p.y = __shfl_xor_sync(0xffffffffu, y.y, 16);
    p.z = __shfl_xor_sync(0xffffffffu, y.z, 16);
    p.w = __shfl_xor_sync(0xffffffffu, y.w, 16);

    float4 c  = *(const float4*)(cosT + (size_t)s * D_ + lane * 4);
    float4 sn = *(const float4*)(sinT + (size_t)s * D_ + lane * 4);
    float sg  = (lane < 16) ? -1.f : 1.f;

    float4 o;
    o.x = fmaf(y.x, c.x, sg * p.x * sn.x);
    o.y = fmaf(y.y, c.y, sg * p.y * sn.y);
    o.z = fmaf(y.z, c.z, sg * p.z * sn.z);
    o.w = fmaf(y.w, c.w, sg * p.w * sn.w);
    *(float4*)(row + lane * 4) = o;
}

// ---------------------------------------------------------------------------
// Flash attention, fp32, causal, GQA (kv head = h/4).
// Block = (q-tile of 64) x (head) x (batch), 256 threads.
// smem: Q[64x128], shared K/V buffer [64x132 padded], S[64x65 padded], m/l/f.
// ---------------------------------------------------------------------------
#define SKV_STRIDE 132
#define SS_STRIDE  65
#define ATTN_SMEM_FLOATS (64 * 128 + 64 * SKV_STRIDE + 64 * SS_STRIDE + 3 * 64)
#define ATTN_SMEM_BYTES  (ATTN_SMEM_FLOATS * 4)

__global__ __launch_bounds__(256, 2) void attn_kernel(
    const float* __restrict__ q, const float* __restrict__ k,
    const float* __restrict__ v, float* __restrict__ ctx)
{
    extern __shared__ float sm[];
    float* sQ  = sm;                       // 64*128
    float* sKV = sQ + 64 * 128;            // 64*132 (K, then reused for V)
    float* sS  = sKV + 64 * SKV_STRIDE;    // 64*65
    float* sM  = sS + 64 * SS_STRIDE;
    float* sL  = sM + 64;
    float* sF  = sL + 64;

    const int tid = threadIdx.x;
    const int qt = blockIdx.x, h = blockIdx.y, b = blockIdx.z;
    const int kvh  = h >> 2;
    const int tok0 = b * S_ + qt * 64;

    // Load Q tile (row-contiguous, stride 32 float4 per row)
    for (int i = tid; i < 64 * 32; i += 256) {
        int r = i >> 5, c4 = i & 31;
        ((float4*)sQ)[r * 32 + c4] =
            *(const float4*)(q + ((size_t)(tok0 + r) * H_ + h) * D_ + c4 * 4);
    }
    if (tid < 64) { sM[tid] = -FLT_MAX; sL[tid] = 0.f; }

    float acc[32];
#pragma unroll
    for (int i = 0; i < 32; i++) acc[i] = 0.f;

    const int aq = tid >> 2;          // 0..63  (query row for PV/epilogue)
    const int ad = (tid & 3) << 5;    // 0/32/64/96 (d chunk)
    const int ty = tid >> 4;          // 0..15  (score q-row base)
    const int tx = (tid & 15) << 2;   // 0..60  (score k-col base)

    for (int kt = 0; kt <= qt; kt++) {
        const int ktok0 = b * S_ + kt * 64;
        __syncthreads();  // previous PV done -> safe to overwrite sKV
        // Load K tile
        for (int i = tid; i < 64 * 32; i += 256) {
            int r = i >> 5, c4 = i & 31;
            ((float4*)sKV)[r * 33 + c4] =
                *(const float4*)(k + ((size_t)(ktok0 + r) * KV_ + kvh) * D_ + c4 * 4);
        }
        __syncthreads();

        // Scores: each thread 4 q-rows x 4 k-cols, dot over D=128 via float4
        float sa[4][4];
#pragma unroll
        for (int r = 0; r < 4; r++)
#pragma unroll
            for (int c = 0; c < 4; c++) sa[r][c] = 0.f;

#pragma unroll 4
        for (int d4 = 0; d4 < 32; d4++) {
            float4 qa[4], ka[4];
#pragma unroll
            for (int r = 0; r < 4; r++)
                qa[r] = ((const float4*)sQ)[(ty + 16 * r) * 32 + d4];
#pragma unroll
            for (int c = 0; c < 4; c++)
                ka[c] = ((const float4*)sKV)[(tx + c) * 33 + d4];
#pragma unroll
            for (int r = 0; r < 4; r++)
#pragma unroll
                for (int c = 0; c < 4; c++) {
                    sa[r][c] = fmaf(qa[r].x, ka[c].x, sa[r][c]);
                    sa[r][c] = fmaf(qa[r].y, ka[c].y, sa[r][c]);
                    sa[r][c] = fmaf(qa[r].z, ka[c].z, sa[r][c]);
                    sa[r][c] = fmaf(qa[r].w, ka[c].w, sa[r][c]);
                }
        }

        const float rsc = 0.08838834764831845f;  // 1/sqrt(128)
        const bool diag = (kt == qt);
#pragma unroll
        for (int r = 0; r < 4; r++) {
            int lq = ty + 16 * r;
#pragma unroll
            for (int c = 0; c < 4; c++) {
                int lk = tx + c;
                float val = sa[r][c] * rsc;
                if (diag && lk > lq) val = -FLT_MAX;
                sS[lq * SS_STRIDE + lk] = val;
            }
        }
        __syncthreads();

        // Overlap: load V tile into sKV (scores already consumed) ...
        for (int i = tid; i < 64 * 32; i += 256) {
            int r = i >> 5, c4 = i & 31;
            ((float4*)sKV)[r * 33 + c4] =
                *(const float4*)(v + ((size_t)(ktok0 + r) * KV_ + kvh) * D_ + c4 * 4);
        }
        // ... while first 2 warps run the online-softmax row update
        if (tid < 64) {
            float mold = sM[tid];
            float* srow = sS + tid * SS_STRIDE;
            float tm = mold;
#pragma unroll 8
            for (int j = 0; j < 64; j++) tm = fmaxf(tm, srow[j]);
            float ps = 0.f;
#pragma unroll 8
            for (int j = 0; j < 64; j++) {
                float pj = __expf(srow[j] - tm);
                srow[j] = pj;
                ps += pj;
            }
            float fsc = __expf(mold - tm);
            sM[tid] = tm;
            sL[tid] = fmaf(sL[tid], fsc, ps);
            sF[tid] = fsc;
        }
        __syncthreads();

        // Rescale accumulator + PV
        float fsc = sF[aq];
#pragma unroll
        for (int i = 0; i < 32; i++) acc[i] *= fsc;
        const float* prow = sS + aq * SS_STRIDE;
#pragma unroll 2
        for (int j = 0; j < 64; j++) {
            float pj = prow[j];
            const float4* v4 = (const float4*)sKV + j * 33 + (ad >> 2);
#pragma unroll
            for (int i4 = 0; i4 < 8; i4++) {
                float4 vv = v4[i4];
                acc[i4 * 4 + 0] = fmaf(pj, vv.x, acc[i4 * 4 + 0]);
                acc[i4 * 4 + 1] = fmaf(pj, vv.y, acc[i4 * 4 + 1]);
                acc[i4 * 4 + 2] = fmaf(pj, vv.z, acc[i4 * 4 + 2]);
                acc[i4 * 4 + 3] = fmaf(pj, vv.w, acc[i4 * 4 + 3]);
            }
        }
    }

    __syncthreads();
    float inv = 1.0f / sL[aq];
    float* op = ctx + ((size_t)(tok0 + aq) * H_ + h) * D_ + ad;
#pragma unroll
    for (int i4 = 0; i4 < 8; i4++) {
        float4 o;
        o.x = acc[i4 * 4 + 0] * inv;
        o.y = acc[i4 * 4 + 1] * inv;
        o.z = acc[i4 * 4 + 2] * inv;
        o.w = acc[i4 * 4 + 3] * inv;
        ((float4*)op)[i4] = o;
    }
}

// ---------------------------------------------------------------------------
// Inputs (metadata order): 0:x 1:mask 2:cos 3:sin 4:Wq 5:bq 6:Wk 7:bk
//                          8:Wv 9:bv 10:Wo 11:q_scale 12:k_scale
// mask is ignored (causal triu(k=1) is baked in).
// ---------------------------------------------------------------------------
extern "C" void kernel_launch(void* const* d_in, const int* in_sizes, int n_in,
                              void* d_out, int out_size)
{
    const float* x    = (const float*)d_in[0];
    const float* cosT = (const float*)d_in[2];
    const float* sinT = (const float*)d_in[3];
    const float* Wq   = (const float*)d_in[4];
    const float* bq   = (const float*)d_in[5];
    const float* Wk   = (const float*)d_in[6];
    const float* bk   = (const float*)d_in[7];
    const float* Wv   = (const float*)d_in[8];
    const float* bv   = (const float*)d_in[9];
    const float* Wo   = (const float*)d_in[10];
    const float* qs   = (const float*)d_in[11];
    const float* ks   = (const float*)d_in[12];
    float* out = (float*)d_out;
    (void)in_sizes; (void)n_in; (void)out_size;

    float *dq = nullptr, *dk = nullptr, *dv = nullptr, *dctx = nullptr;
    cudaGetSymbolAddress((void**)&dq, g_q);
    cudaGetSymbolAddress((void**)&dk, g_k);
    cudaGetSymbolAddress((void**)&dv, g_v);
    cudaGetSymbolAddress((void**)&dctx, g_ctx);

    cudaFuncSetAttribute(attn_kernel,
                         cudaFuncAttributeMaxDynamicSharedMemorySize,
                         ATTN_SMEM_BYTES);

    dim3 blk(256);
    // QKV projections
    sgemm_bias_kernel<<<dim3((H_ * D_) / 128, NTOK / 128), blk>>>(
        x, Wq, bq, dq, NTOK, H_ * D_, E_);
    sgemm_bias_kernel<<<dim3((KV_ * D_) / 128, NTOK / 128), blk>>>(
        x, Wk, bk, dk, NTOK, KV_ * D_, E_);
    sgemm_bias_kernel<<<dim3((KV_ * D_) / 128, NTOK / 128), blk>>>(
        x, Wv, bv, dv, NTOK, KV_ * D_, E_);
    // RMSNorm + RoPE
    rmsrope_kernel<<<(NTOK * H_ * 32) / 256, blk>>>(dq, cosT, sinT, qs, H_);
    rmsrope_kernel<<<(NTOK * KV_ * 32) / 256, blk>>>(dk, cosT, sinT, ks, KV_);
    // Attention
    attn_kernel<<<dim3(S_ / 64, H_, B_), blk, ATTN_SMEM_BYTES>>>(dq, dk, dv, dctx);
    // Output projection
    sgemm_bias_kernel<<<dim3(E_ / 128, NTOK / 128), blk>>>(
        dctx, Wo, nullptr, out, NTOK, E_, H_ * D_);
}

// round 4
// speedup vs baseline: 1.1928x; 1.1928x over previous
#include <cuda_runtime.h>
#include <cuda_bf16.h>
#include <math.h>
#include <float.h>
#include <stdint.h>

#define B_   2
#define S_   2048
#define E_   2048
#define H_   32
#define KV_  8
#define D_   128
#define NTOK (B_ * S_)
#define HD_  (H_ * D_)   // 4096
#define KVD_ (KV_ * D_)  // 1024

// ---------------------------------------------------------------------------
// Scratch (__device__ globals; no cudaMalloc allowed)
// ---------------------------------------------------------------------------
__device__ float g_q[(size_t)NTOK * HD_];
__device__ float g_k[(size_t)NTOK * KVD_];
__device__ float g_v[(size_t)NTOK * KVD_];
__device__ float g_ctx[(size_t)NTOK * HD_];

// split-bf16 activations (hi/lo decomposition of fp32)
__device__ __nv_bfloat16 g_xh[(size_t)NTOK * E_],  g_xl[(size_t)NTOK * E_];
__device__ __nv_bfloat16 g_ch[(size_t)NTOK * HD_], g_cl[(size_t)NTOK * HD_];
// transposed weights, K-major [N][K], split
__device__ __nv_bfloat16 g_wqh[(size_t)HD_ * E_],  g_wql[(size_t)HD_ * E_];
__device__ __nv_bfloat16 g_wkh[(size_t)KVD_ * E_], g_wkl[(size_t)KVD_ * E_];
__device__ __nv_bfloat16 g_wvh[(size_t)KVD_ * E_], g_wvl[(size_t)KVD_ * E_];
__device__ __nv_bfloat16 g_woh[(size_t)E_ * HD_],  g_wol[(size_t)E_ * HD_];

// ---------------------------------------------------------------------------
// Base-target tensor-core primitives (sm_80-level; compile at compute_103)
// ---------------------------------------------------------------------------
__device__ __forceinline__ uint32_t smem_u32(const void* p) {
    uint32_t a;
    asm("{ .reg .u64 t; cvta.to.shared.u64 t, %1; cvt.u32.u64 %0, t; }" : "=r"(a) : "l"(p));
    return a;
}
__device__ __forceinline__ void ldsm4(uint32_t& r0, uint32_t& r1, uint32_t& r2,
                                      uint32_t& r3, uint32_t addr) {
    asm volatile("ldmatrix.sync.aligned.m8n8.x4.shared.b16 {%0,%1,%2,%3}, [%4];"
                 : "=r"(r0), "=r"(r1), "=r"(r2), "=r"(r3) : "r"(addr));
}
__device__ __forceinline__ void mma_bf16(float* c, uint32_t a0, uint32_t a1,
                                         uint32_t a2, uint32_t a3,
                                         uint32_t b0, uint32_t b1) {
    asm volatile(
        "mma.sync.aligned.m16n8k16.row.col.f32.bf16.bf16.f32 "
        "{%0,%1,%2,%3}, {%4,%5,%6,%7}, {%8,%9}, {%0,%1,%2,%3};"
        : "+f"(c[0]), "+f"(c[1]), "+f"(c[2]), "+f"(c[3])
        : "r"(a0), "r"(a1), "r"(a2), "r"(a3), "r"(b0), "r"(b1));
}

// ---------------------------------------------------------------------------
// split: fp32 -> (hi, lo) bf16
// ---------------------------------------------------------------------------
__global__ __launch_bounds__(256) void split_kernel(
    const float* __restrict__ src, __nv_bfloat16* __restrict__ h,
    __nv_bfloat16* __restrict__ l, int n)
{
    int i = blockIdx.x * 256 + threadIdx.x;
    if (i < n) {
        float v = src[i];
        __nv_bfloat16 hh = __float2bfloat16(v);
        h[i] = hh;
        l[i] = __float2bfloat16(v - __bfloat162float(hh));
    }
}

// ---------------------------------------------------------------------------
// transpose + split: W [K][N] fp32 -> Th/Tl [N][K] bf16 (K-major for mma.row.col)
// ---------------------------------------------------------------------------
__global__ __launch_bounds__(256) void transpose_split_kernel(
    const float* __restrict__ W, __nv_bfloat16* __restrict__ Th,
    __nv_bfloat16* __restrict__ Tl, int K, int N)
{
    __shared__ float t[32][33];
    int n = blockIdx.x * 32 + threadIdx.x;
    int k0 = blockIdx.y * 32;
    for (int j = threadIdx.y; j < 32; j += 8)
        t[j][threadIdx.x] = W[(size_t)(k0 + j) * N + n];
    __syncthreads();
    int k = k0 + threadIdx.x;
    for (int j = threadIdx.y; j < 32; j += 8) {
        float v = t[threadIdx.x][j];
        int nn = blockIdx.x * 32 + j;
        __nv_bfloat16 hh = __float2bfloat16(v);
        Th[(size_t)nn * K + k] = hh;
        Tl[(size_t)nn * K + k] = __float2bfloat16(v - __bfloat162float(hh));
    }
}

// ---------------------------------------------------------------------------
// HMMA GEMM: C[M,N] = (Ah+Al)[M,K] @ (Bh+Bl)[N,K]^T (+bias), fp32 accum.
// 3-term split-bf16 (hh + hl + lh). Block tile 128x128, BK=64, 8 warps
// (warp tile 64x32). Smem rows padded to 144B -> ldmatrix conflict-free.
// ---------------------------------------------------------------------------
#define AS_B   144                 // smem bytes per 64-bf16 row (128 + 16 pad)
#define TILE_B (128 * AS_B)        // 18432 per tile
#define GSM_AH 0
#define GSM_AL (TILE_B)
#define GSM_BH (2 * TILE_B)
#define GSM_BL (3 * TILE_B)
#define GSM_TOTAL (4 * TILE_B)     // 73728 bytes

__global__ __launch_bounds__(256, 2) void gemm_hmma_kernel(
    const __nv_bfloat16* __restrict__ Ah, const __nv_bfloat16* __restrict__ Al,
    const __nv_bfloat16* __restrict__ Bh, const __nv_bfloat16* __restrict__ Bl,
    const float* __restrict__ bias, float* __restrict__ C,
    int M, int N, int K)
{
    extern __shared__ char smem[];
    const uint32_t sbase = smem_u32(smem);
    const int tid  = threadIdx.x;
    const int wid  = tid >> 5, lane = tid & 31;
    const int m0   = blockIdx.y * 128, n0 = blockIdx.x * 128;
    const int wm   = (wid >> 2) * 64;   // warp m-offset (0/64)
    const int wn   = (wid & 3) * 32;    // warp n-offset (0/32/64/96)

    float acc[4][4][4];
#pragma unroll
    for (int i = 0; i < 4; i++)
#pragma unroll
        for (int j = 0; j < 4; j++)
#pragma unroll
            for (int f = 0; f < 4; f++) acc[i][j][f] = 0.f;

    // gmem->smem copy mapping: thread -> (row lr+32t, 16B chunk lcB)
    const int lr  = tid >> 3;
    const int lcB = (tid & 7) << 4;     // byte offset within 128B row

    // ldmatrix per-lane address components
    const int a_row = wm + (lane & 7) + ((lane >> 3) & 1) * 8;  // + mt*16
    const int a_kB  = (lane >> 4) * 16;                          // + ks*32
    const int seg   = lane >> 3;
    const int b_row = wn + (lane & 7) + (seg >> 1) * 8;          // + bt*16
    const int b_kB  = (seg & 1) * 16;                            // + ks*32

    for (int k0 = 0; k0 < K; k0 += 64) {
        // ---- load 4 tiles: [128 rows][64 bf16], row stride 144B ----
#pragma unroll
        for (int t = 0; t < 4; t++) {
            int r = lr + t * 32;
            size_t ga = ((size_t)(m0 + r) * K + k0) * 2 + lcB;
            size_t gb = ((size_t)(n0 + r) * K + k0) * 2 + lcB;
            int so = r * AS_B + lcB;
            *(uint4*)(smem + GSM_AH + so) = *(const uint4*)((const char*)Ah + ga);
            *(uint4*)(smem + GSM_AL + so) = *(const uint4*)((const char*)Al + ga);
            *(uint4*)(smem + GSM_BH + so) = *(const uint4*)((const char*)Bh + gb);
            *(uint4*)(smem + GSM_BL + so) = *(const uint4*)((const char*)Bl + gb);
        }
        __syncthreads();

        // ---- 4 k-steps of 16 ----
#pragma unroll
        for (int ks = 0; ks < 4; ks++) {
            const int kB = ks * 32;
            uint32_t af[4][4], bh[4][2], bl[4][2];
            // A_h fragments (4 m16 tiles)
#pragma unroll
            for (int mt = 0; mt < 4; mt++)
                ldsm4(af[mt][0], af[mt][1], af[mt][2], af[mt][3],
                      sbase + GSM_AH + (a_row + mt * 16) * AS_B + kB + a_kB);
            // B_h fragments (4 n8 tiles via 2 x ldsm4)
#pragma unroll
            for (int bt = 0; bt < 2; bt++) {
                uint32_t r0, r1, r2, r3;
                ldsm4(r0, r1, r2, r3,
                      sbase + GSM_BH + (b_row + bt * 16) * AS_B + kB + b_kB);
                bh[bt * 2][0] = r0; bh[bt * 2][1] = r1;
                bh[bt * 2 + 1][0] = r2; bh[bt * 2 + 1][1] = r3;
            }
            // term 1: Ah * Bh
#pragma unroll
            for (int mt = 0; mt < 4; mt++)
#pragma unroll
                for (int nt = 0; nt < 4; nt++)
                    mma_bf16(acc[mt][nt], af[mt][0], af[mt][1], af[mt][2],
                             af[mt][3], bh[nt][0], bh[nt][1]);
            // B_l fragments
#pragma unroll
            for (int bt = 0; bt < 2; bt++) {
                uint32_t r0, r1, r2, r3;
                ldsm4(r0, r1, r2, r3,
                      sbase + GSM_BL + (b_row + bt * 16) * AS_B + kB + b_kB);
                bl[bt * 2][0] = r0; bl[bt * 2][1] = r1;
                bl[bt * 2 + 1][0] = r2; bl[bt * 2 + 1][1] = r3;
            }
            // term 2: Ah * Bl
#pragma unroll
            for (int mt = 0; mt < 4; mt++)
#pragma unroll
                for (int nt = 0; nt < 4; nt++)
                    mma_bf16(acc[mt][nt], af[mt][0], af[mt][1], af[mt][2],
                             af[mt][3], bl[nt][0], bl[nt][1]);
            // A_l fragments (overwrite af)
#pragma unroll
            for (int mt = 0; mt < 4; mt++)
                ldsm4(af[mt][0], af[mt][1], af[mt][2], af[mt][3],
                      sbase + GSM_AL + (a_row + mt * 16) * AS_B + kB + a_kB);
            // term 3: Al * Bh
#pragma unroll
            for (int mt = 0; mt < 4; mt++)
#pragma unroll
                for (int nt = 0; nt < 4; nt++)
                    mma_bf16(acc[mt][nt], af[mt][0], af[mt][1], af[mt][2],
                             af[mt][3], bh[nt][0], bh[nt][1]);
        }
        __syncthreads();
    }

    // ---- epilogue: fragment (lane>>2 row, (lane&3)*2 col) + bias ----
#pragma unroll
    for (int nt = 0; nt < 4; nt++) {
        int col = n0 + wn + nt * 8 + (lane & 3) * 2;
        float b0 = bias ? bias[col] : 0.f;
        float b1 = bias ? bias[col + 1] : 0.f;
#pragma unroll
        for (int mt = 0; mt < 4; mt++) {
            int row = m0 + wm + mt * 16 + (lane >> 2);
            float2 v0 = {acc[mt][nt][0] + b0, acc[mt][nt][1] + b1};
            float2 v1 = {acc[mt][nt][2] + b0, acc[mt][nt][3] + b1};
            *(float2*)(C + (size_t)row * N + col) = v0;
            *(float2*)(C + (size_t)(row + 8) * N + col) = v1;
        }
    }
}

// ---------------------------------------------------------------------------
// Fused RMSNorm + RoPE (unchanged)
// ---------------------------------------------------------------------------
__global__ __launch_bounds__(256) void rmsrope_kernel(
    float* __restrict__ t, const float* __restrict__ cosT,
    const float* __restrict__ sinT, const float* __restrict__ scale, int heads)
{
    int gw   = (blockIdx.x * 256 + threadIdx.x) >> 5;
    int lane = threadIdx.x & 31;
    if (gw >= NTOK * heads) return;
    int token = gw / heads;
    int h     = gw - token * heads;
    int s     = token & (S_ - 1);

    float* row = t + ((size_t)token * heads + h) * D_;
    float4 x = *(const float4*)(row + lane * 4);

    float ss = fmaf(x.x, x.x, fmaf(x.y, x.y, fmaf(x.z, x.z, x.w * x.w)));
#pragma unroll
    for (int o = 16; o; o >>= 1) ss += __shfl_xor_sync(0xffffffffu, ss, o);
    float r = rsqrtf(ss * (1.0f / D_) + 1e-6f);

    float4 sc = *(const float4*)(scale + lane * 4);
    float4 y;
    y.x = x.x * r * sc.x; y.y = x.y * r * sc.y;
    y.z = x.z * r * sc.z; y.w = x.w * r * sc.w;

    float4 p;
    p.x = __shfl_xor_sync(0xffffffffu, y.x, 16);
    p.y = __shfl_xor_sync(0xffffffffu, y.y, 16);
    p.z = __shfl_xor_sync(0xffffffffu, y.z, 16);
    p.w = __shfl_xor_sync(0xffffffffu, y.w, 16);

    float4 c  = *(const float4*)(cosT + (size_t)s * D_ + lane * 4);
    float4 sn = *(const float4*)(sinT + (size_t)s * D_ + lane * 4);
    float sg  = (lane < 16) ? -1.f : 1.f;

    float4 o;
    o.x = fmaf(y.x, c.x, sg * p.x * sn.x);
    o.y = fmaf(y.y, c.y, sg * p.y * sn.y);
    o.z = fmaf(y.z, c.z, sg * p.z * sn.z);
    o.w = fmaf(y.w, c.w, sg * p.w * sn.w);
    *(float4*)(row + lane * 4) = o;
}

// ---------------------------------------------------------------------------
// Flash attention fp32 (unchanged; HMMA rewrite is the next candidate once
// this round's ncu pins down the tensor-pipe rate)
// ---------------------------------------------------------------------------
#define SKV_STRIDE 132
#define SS_STRIDE  65
#define ATTN_SMEM_FLOATS (64 * 128 + 64 * SKV_STRIDE + 64 * SS_STRIDE + 3 * 64)
#define ATTN_SMEM_BYTES  (ATTN_SMEM_FLOATS * 4)

__global__ __launch_bounds__(256, 2) void attn_kernel(
    const float* __restrict__ q, const float* __restrict__ k,
    const float* __restrict__ v, float* __restrict__ ctx)
{
    extern __shared__ float sm[];
    float* sQ  = sm;
    float* sKV = sQ + 64 * 128;
    float* sS  = sKV + 64 * SKV_STRIDE;
    float* sM  = sS + 64 * SS_STRIDE;
    float* sL  = sM + 64;
    float* sF  = sL + 64;

    const int tid = threadIdx.x;
    const int qt = blockIdx.x, h = blockIdx.y, b = blockIdx.z;
    const int kvh  = h >> 2;
    const int tok0 = b * S_ + qt * 64;

    for (int i = tid; i < 64 * 32; i += 256) {
        int r = i >> 5, c4 = i & 31;
        ((float4*)sQ)[r * 32 + c4] =
            *(const float4*)(q + ((size_t)(tok0 + r) * H_ + h) * D_ + c4 * 4);
    }
    if (tid < 64) { sM[tid] = -FLT_MAX; sL[tid] = 0.f; }

    float acc[32];
#pragma unroll
    for (int i = 0; i < 32; i++) acc[i] = 0.f;

    const int aq = tid >> 2;
    const int ad = (tid & 3) << 5;
    const int ty = tid >> 4;
    const int tx = (tid & 15) << 2;

    for (int kt = 0; kt <= qt; kt++) {
        const int ktok0 = b * S_ + kt * 64;
        __syncthreads();
        for (int i = tid; i < 64 * 32; i += 256) {
            int r = i >> 5, c4 = i & 31;
            ((float4*)sKV)[r * 33 + c4] =
                *(const float4*)(k + ((size_t)(ktok0 + r) * KV_ + kvh) * D_ + c4 * 4);
        }
        __syncthreads();

        float sa[4][4];
#pragma unroll
        for (int r = 0; r < 4; r++)
#pragma unroll
            for (int c = 0; c < 4; c++) sa[r][c] = 0.f;

#pragma unroll 4
        for (int d4 = 0; d4 < 32; d4++) {
            float4 qa[4], ka[4];
#pragma unroll
            for (int r = 0; r < 4; r++)
                qa[r] = ((const float4*)sQ)[(ty + 16 * r) * 32 + d4];
#pragma unroll
            for (int c = 0; c < 4; c++)
                ka[c] = ((const float4*)sKV)[(tx + c) * 33 + d4];
#pragma unroll
            for (int r = 0; r < 4; r++)
#pragma unroll
                for (int c = 0; c < 4; c++) {
                    sa[r][c] = fmaf(qa[r].x, ka[c].x, sa[r][c]);
                    sa[r][c] = fmaf(qa[r].y, ka[c].y, sa[r][c]);
                    sa[r][c] = fmaf(qa[r].z, ka[c].z, sa[r][c]);
                    sa[r][c] = fmaf(qa[r].w, ka[c].w, sa[r][c]);
                }
        }

        const float rsc = 0.08838834764831845f;
        const bool diag = (kt == qt);
#pragma unroll
        for (int r = 0; r < 4; r++) {
            int lq = ty + 16 * r;
#pragma unroll
            for (int c = 0; c < 4; c++) {
                int lk = tx + c;
                float val = sa[r][c] * rsc;
                if (diag && lk > lq) val = -FLT_MAX;
                sS[lq * SS_STRIDE + lk] = val;
            }
        }
        __syncthreads();

        for (int i = tid; i < 64 * 32; i += 256) {
            int r = i >> 5, c4 = i & 31;
            ((float4*)sKV)[r * 33 + c4] =
                *(const float4*)(v + ((size_t)(ktok0 + r) * KV_ + kvh) * D_ + c4 * 4);
        }
        if (tid < 64) {
            float mold = sM[tid];
            float* srow = sS + tid * SS_STRIDE;
            float tm = mold;
#pragma unroll 8
            for (int j = 0; j < 64; j++) tm = fmaxf(tm, srow[j]);
            float ps = 0.f;
#pragma unroll 8
            for (int j = 0; j < 64; j++) {
                float pj = __expf(srow[j] - tm);
                srow[j] = pj;
                ps += pj;
            }
            float fsc = __expf(mold - tm);
            sM[tid] = tm;
            sL[tid] = fmaf(sL[tid], fsc, ps);
            sF[tid] = fsc;
        }
        __syncthreads();

        float fsc = sF[aq];
#pragma unroll
        for (int i = 0; i < 32; i++) acc[i] *= fsc;
        const float* prow = sS + aq * SS_STRIDE;
#pragma unroll 2
        for (int j = 0; j < 64; j++) {
            float pj = prow[j];
            const float4* v4 = (const float4*)sKV + j * 33 + (ad >> 2);
#pragma unroll
            for (int i4 = 0; i4 < 8; i4++) {
                float4 vv = v4[i4];
                acc[i4 * 4 + 0] = fmaf(pj, vv.x, acc[i4 * 4 + 0]);
                acc[i4 * 4 + 1] = fmaf(pj, vv.y, acc[i4 * 4 + 1]);
                acc[i4 * 4 + 2] = fmaf(pj, vv.z, acc[i4 * 4 + 2]);
                acc[i4 * 4 + 3] = fmaf(pj, vv.w, acc[i4 * 4 + 3]);
            }
        }
    }

    __syncthreads();
    float inv = 1.0f / sL[aq];
    float* op = ctx + ((size_t)(tok0 + aq) * H_ + h) * D_ + ad;
#pragma unroll
    for (int i4 = 0; i4 < 8; i4++) {
        float4 o;
        o.x = acc[i4 * 4 + 0] * inv;
        o.y = acc[i4 * 4 + 1] * inv;
        o.z = acc[i4 * 4 + 2] * inv;
        o.w = acc[i4 * 4 + 3] * inv;
        ((float4*)op)[i4] = o;
    }
}

// ---------------------------------------------------------------------------
// Inputs: 0:x 1:mask 2:cos 3:sin 4:Wq 5:bq 6:Wk 7:bk 8:Wv 9:bv 10:Wo 11:qs 12:ks
// ---------------------------------------------------------------------------
extern "C" void kernel_launch(void* const* d_in, const int* in_sizes, int n_in,
                              void* d_out, int out_size)
{
    const float* x    = (const float*)d_in[0];
    const float* cosT = (const float*)d_in[2];
    const float* sinT = (const float*)d_in[3];
    const float* Wq   = (const float*)d_in[4];
    const float* bq   = (const float*)d_in[5];
    const float* Wk   = (const float*)d_in[6];
    const float* bk   = (const float*)d_in[7];
    const float* Wv   = (const float*)d_in[8];
    const float* bv   = (const float*)d_in[9];
    const float* Wo   = (const float*)d_in[10];
    const float* qs   = (const float*)d_in[11];
    const float* ks   = (const float*)d_in[12];
    float* out = (float*)d_out;
    (void)in_sizes; (void)n_in; (void)out_size;

    float *dq, *dk, *dv, *dctx;
    cudaGetSymbolAddress((void**)&dq, g_q);
    cudaGetSymbolAddress((void**)&dk, g_k);
    cudaGetSymbolAddress((void**)&dv, g_v);
    cudaGetSymbolAddress((void**)&dctx, g_ctx);
    __nv_bfloat16 *xh, *xl, *ch, *cl, *wqh, *wql, *wkh, *wkl, *wvh, *wvl, *woh, *wol;
    cudaGetSymbolAddress((void**)&xh, g_xh);   cudaGetSymbolAddress((void**)&xl, g_xl);
    cudaGetSymbolAddress((void**)&ch, g_ch);   cudaGetSymbolAddress((void**)&cl, g_cl);
    cudaGetSymbolAddress((void**)&wqh, g_wqh); cudaGetSymbolAddress((void**)&wql, g_wql);
    cudaGetSymbolAddress((void**)&wkh, g_wkh); cudaGetSymbolAddress((void**)&wkl, g_wkl);
    cudaGetSymbolAddress((void**)&wvh, g_wvh); cudaGetSymbolAddress((void**)&wvl, g_wvl);
    cudaGetSymbolAddress((void**)&woh, g_woh); cudaGetSymbolAddress((void**)&wol, g_wol);

    cudaFuncSetAttribute(attn_kernel, cudaFuncAttributeMaxDynamicSharedMemorySize,
                         ATTN_SMEM_BYTES);
    cudaFuncSetAttribute(gemm_hmma_kernel, cudaFuncAttributeMaxDynamicSharedMemorySize,
                         GSM_TOTAL);

    dim3 t256(256);
    dim3 t32x8(32, 8);

    // 0: split x
    split_kernel<<<(NTOK * E_) / 256, t256>>>(x, xh, xl, NTOK * E_);
    // 1-4: transpose+split weights  W[K][N] -> [N][K]
    transpose_split_kernel<<<dim3(HD_ / 32, E_ / 32), t32x8>>>(Wq, wqh, wql, E_, HD_);
    transpose_split_kernel<<<dim3(KVD_ / 32, E_ / 32), t32x8>>>(Wk, wkh, wkl, E_, KVD_);
    transpose_split_kernel<<<dim3(KVD_ / 32, E_ / 32), t32x8>>>(Wv, wvh, wvl, E_, KVD_);
    transpose_split_kernel<<<dim3(E_ / 32, HD_ / 32), t32x8>>>(Wo, woh, wol, HD_, E_);
    // 5-7: projection GEMMs (HMMA)
    gemm_hmma_kernel<<<dim3(HD_ / 128, NTOK / 128), t256, GSM_TOTAL>>>(
        xh, xl, wqh, wql, bq, dq, NTOK, HD_, E_);
    gemm_hmma_kernel<<<dim3(KVD_ / 128, NTOK / 128), t256, GSM_TOTAL>>>(
        xh, xl, wkh, wkl, bk, dk, NTOK, KVD_, E_);
    gemm_hmma_kernel<<<dim3(KVD_ / 128, NTOK / 128), t256, GSM_TOTAL>>>(
        xh, xl, wvh, wvl, bv, dv, NTOK, KVD_, E_);
    // 8-9: RMSNorm + RoPE
    rmsrope_kernel<<<(NTOK * H_ * 32) / 256, t256>>>(dq, cosT, sinT, qs, H_);
    rmsrope_kernel<<<(NTOK * KV_ * 32) / 256, t256>>>(dk, cosT, sinT, ks, KV_);
    // 10: attention
    attn_kernel<<<dim3(S_ / 64, H_, B_), t256, ATTN_SMEM_BYTES>>>(dq, dk, dv, dctx);
    // 11: split ctx
    split_kernel<<<(NTOK * HD_) / 256, t256>>>(dctx, ch, cl, NTOK * HD_);
    // 12: output GEMM
    gemm_hmma_kernel<<<dim3(E_ / 128, NTOK / 128), t256, GSM_TOTAL>>>(
        ch, cl, woh, wol, nullptr, out, NTOK, E_, HD_);
}

// round 5
// speedup vs baseline: 5.8131x; 4.8733x over previous
#include <cuda_runtime.h>
#include <cuda_bf16.h>
#include <math.h>
#include <float.h>
#include <stdint.h>

#define B_   2
#define S_   2048
#define E_   2048
#define H_   32
#define KV_  8
#define D_   128
#define NTOK (B_ * S_)
#define HD_  (H_ * D_)   // 4096
#define KVD_ (KV_ * D_)  // 1024

// ---------------------------------------------------------------------------
// Scratch
// ---------------------------------------------------------------------------
__device__ float g_q[(size_t)NTOK * HD_];
__device__ float g_k[(size_t)NTOK * KVD_];
__device__ float g_v[(size_t)NTOK * KVD_];
__device__ float g_ctx[(size_t)NTOK * HD_];

__device__ __nv_bfloat16 g_xh[(size_t)NTOK * E_],  g_xl[(size_t)NTOK * E_];
__device__ __nv_bfloat16 g_ch[(size_t)NTOK * HD_], g_cl[(size_t)NTOK * HD_];
__device__ __nv_bfloat16 g_wqh[(size_t)HD_ * E_],  g_wql[(size_t)HD_ * E_];
__device__ __nv_bfloat16 g_wkh[(size_t)KVD_ * E_], g_wkl[(size_t)KVD_ * E_];
__device__ __nv_bfloat16 g_wvh[(size_t)KVD_ * E_], g_wvl[(size_t)KVD_ * E_];
__device__ __nv_bfloat16 g_woh[(size_t)E_ * HD_],  g_wol[(size_t)E_ * HD_];
// attention operands, split bf16
__device__ __nv_bfloat16 g_qh[(size_t)NTOK * HD_],  g_ql[(size_t)NTOK * HD_];
__device__ __nv_bfloat16 g_kh[(size_t)NTOK * KVD_], g_kl[(size_t)NTOK * KVD_];
__device__ __nv_bfloat16 g_vh[(size_t)NTOK * KVD_], g_vl[(size_t)NTOK * KVD_];

// ---------------------------------------------------------------------------
// Tensor-core primitives (base target, compile at compute_103)
// ---------------------------------------------------------------------------
__device__ __forceinline__ uint32_t smem_u32(const void* p) {
    uint32_t a;
    asm("{ .reg .u64 t; cvta.to.shared.u64 t, %1; cvt.u32.u64 %0, t; }" : "=r"(a) : "l"(p));
    return a;
}
__device__ __forceinline__ void ldsm4(uint32_t& r0, uint32_t& r1, uint32_t& r2,
                                      uint32_t& r3, uint32_t addr) {
    asm volatile("ldmatrix.sync.aligned.m8n8.x4.shared.b16 {%0,%1,%2,%3}, [%4];"
                 : "=r"(r0), "=r"(r1), "=r"(r2), "=r"(r3) : "r"(addr));
}
__device__ __forceinline__ void ldsm4t(uint32_t& r0, uint32_t& r1, uint32_t& r2,
                                       uint32_t& r3, uint32_t addr) {
    asm volatile("ldmatrix.sync.aligned.m8n8.x4.trans.shared.b16 {%0,%1,%2,%3}, [%4];"
                 : "=r"(r0), "=r"(r1), "=r"(r2), "=r"(r3) : "r"(addr));
}
__device__ __forceinline__ void mma_bf16(float* c, uint32_t a0, uint32_t a1,
                                         uint32_t a2, uint32_t a3,
                                         uint32_t b0, uint32_t b1) {
    asm volatile(
        "mma.sync.aligned.m16n8k16.row.col.f32.bf16.bf16.f32 "
        "{%0,%1,%2,%3}, {%4,%5,%6,%7}, {%8,%9}, {%0,%1,%2,%3};"
        : "+f"(c[0]), "+f"(c[1]), "+f"(c[2]), "+f"(c[3])
        : "r"(a0), "r"(a1), "r"(a2), "r"(a3), "r"(b0), "r"(b1));
}

// ---------------------------------------------------------------------------
// split: fp32 -> (hi, lo) bf16
// ---------------------------------------------------------------------------
__global__ __launch_bounds__(256) void split_kernel(
    const float* __restrict__ src, __nv_bfloat16* __restrict__ h,
    __nv_bfloat16* __restrict__ l, int n)
{
    int i = blockIdx.x * 256 + threadIdx.x;
    if (i < n) {
        float v = src[i];
        __nv_bfloat16 hh = __float2bfloat16(v);
        h[i] = hh;
        l[i] = __float2bfloat16(v - __bfloat162float(hh));
    }
}

// ---------------------------------------------------------------------------
// transpose + split: W [K][N] fp32 -> Th/Tl [N][K] bf16
// ---------------------------------------------------------------------------
__global__ __launch_bounds__(256) void transpose_split_kernel(
    const float* __restrict__ W, __nv_bfloat16* __restrict__ Th,
    __nv_bfloat16* __restrict__ Tl, int K, int N)
{
    __shared__ float t[32][33];
    int n = blockIdx.x * 32 + threadIdx.x;
    int k0 = blockIdx.y * 32;
    for (int j = threadIdx.y; j < 32; j += 8)
        t[j][threadIdx.x] = W[(size_t)(k0 + j) * N + n];
    __syncthreads();
    int k = k0 + threadIdx.x;
    for (int j = threadIdx.y; j < 32; j += 8) {
        float v = t[threadIdx.x][j];
        int nn = blockIdx.x * 32 + j;
        __nv_bfloat16 hh = __float2bfloat16(v);
        Th[(size_t)nn * K + k] = hh;
        Tl[(size_t)nn * K + k] = __float2bfloat16(v - __bfloat162float(hh));
    }
}

// ---------------------------------------------------------------------------
// HMMA GEMM (unchanged from R4 — validated): 3-term split-bf16
// ---------------------------------------------------------------------------
#define AS_B   144
#define TILE_B (128 * AS_B)
#define GSM_AH 0
#define GSM_AL (TILE_B)
#define GSM_BH (2 * TILE_B)
#define GSM_BL (3 * TILE_B)
#define GSM_TOTAL (4 * TILE_B)

__global__ __launch_bounds__(256, 2) void gemm_hmma_kernel(
    const __nv_bfloat16* __restrict__ Ah, const __nv_bfloat16* __restrict__ Al,
    const __nv_bfloat16* __restrict__ Bh, const __nv_bfloat16* __restrict__ Bl,
    const float* __restrict__ bias, float* __restrict__ C,
    int M, int N, int K)
{
    extern __shared__ char smem[];
    const uint32_t sbase = smem_u32(smem);
    const int tid  = threadIdx.x;
    const int wid  = tid >> 5, lane = tid & 31;
    const int m0   = blockIdx.y * 128, n0 = blockIdx.x * 128;
    const int wm   = (wid >> 2) * 64;
    const int wn   = (wid & 3) * 32;

    float acc[4][4][4];
#pragma unroll
    for (int i = 0; i < 4; i++)
#pragma unroll
        for (int j = 0; j < 4; j++)
#pragma unroll
            for (int f = 0; f < 4; f++) acc[i][j][f] = 0.f;

    const int lr  = tid >> 3;
    const int lcB = (tid & 7) << 4;

    const int a_row = wm + (lane & 7) + ((lane >> 3) & 1) * 8;
    const int a_kB  = (lane >> 4) * 16;
    const int seg   = lane >> 3;
    const int b_row = wn + (lane & 7) + (seg >> 1) * 8;
    const int b_kB  = (seg & 1) * 16;

    for (int k0 = 0; k0 < K; k0 += 64) {
#pragma unroll
        for (int t = 0; t < 4; t++) {
            int r = lr + t * 32;
            size_t ga = ((size_t)(m0 + r) * K + k0) * 2 + lcB;
            size_t gb = ((size_t)(n0 + r) * K + k0) * 2 + lcB;
            int so = r * AS_B + lcB;
            *(uint4*)(smem + GSM_AH + so) = *(const uint4*)((const char*)Ah + ga);
            *(uint4*)(smem + GSM_AL + so) = *(const uint4*)((const char*)Al + ga);
            *(uint4*)(smem + GSM_BH + so) = *(const uint4*)((const char*)Bh + gb);
            *(uint4*)(smem + GSM_BL + so) = *(const uint4*)((const char*)Bl + gb);
        }
        __syncthreads();

#pragma unroll
        for (int ks = 0; ks < 4; ks++) {
            const int kB = ks * 32;
            uint32_t af[4][4], bh[4][2], bl[4][2];
#pragma unroll
            for (int mt = 0; mt < 4; mt++)
                ldsm4(af[mt][0], af[mt][1], af[mt][2], af[mt][3],
                      sbase + GSM_AH + (a_row + mt * 16) * AS_B + kB + a_kB);
#pragma unroll
            for (int bt = 0; bt < 2; bt++) {
                uint32_t r0, r1, r2, r3;
                ldsm4(r0, r1, r2, r3,
                      sbase + GSM_BH + (b_row + bt * 16) * AS_B + kB + b_kB);
                bh[bt * 2][0] = r0; bh[bt * 2][1] = r1;
                bh[bt * 2 + 1][0] = r2; bh[bt * 2 + 1][1] = r3;
            }
#pragma unroll
            for (int mt = 0; mt < 4; mt++)
#pragma unroll
                for (int nt = 0; nt < 4; nt++)
                    mma_bf16(acc[mt][nt], af[mt][0], af[mt][1], af[mt][2],
                             af[mt][3], bh[nt][0], bh[nt][1]);
#pragma unroll
            for (int bt = 0; bt < 2; bt++) {
                uint32_t r0, r1, r2, r3;
                ldsm4(r0, r1, r2, r3,
                      sbase + GSM_BL + (b_row + bt * 16) * AS_B + kB + b_kB);
                bl[bt * 2][0] = r0; bl[bt * 2][1] = r1;
                bl[bt * 2 + 1][0] = r2; bl[bt * 2 + 1][1] = r3;
            }
#pragma unroll
            for (int mt = 0; mt < 4; mt++)
#pragma unroll
                for (int nt = 0; nt < 4; nt++)
                    mma_bf16(acc[mt][nt], af[mt][0], af[mt][1], af[mt][2],
                             af[mt][3], bl[nt][0], bl[nt][1]);
#pragma unroll
            for (int mt = 0; mt < 4; mt++)
                ldsm4(af[mt][0], af[mt][1], af[mt][2], af[mt][3],
                      sbase + GSM_AL + (a_row + mt * 16) * AS_B + kB + a_kB);
#pragma unroll
            for (int mt = 0; mt < 4; mt++)
#pragma unroll
                for (int nt = 0; nt < 4; nt++)
                    mma_bf16(acc[mt][nt], af[mt][0], af[mt][1], af[mt][2],
                             af[mt][3], bh[nt][0], bh[nt][1]);
        }
        __syncthreads();
    }

#pragma unroll
    for (int nt = 0; nt < 4; nt++) {
        int col = n0 + wn + nt * 8 + (lane & 3) * 2;
        float b0 = bias ? bias[col] : 0.f;
        float b1 = bias ? bias[col + 1] : 0.f;
#pragma unroll
        for (int mt = 0; mt < 4; mt++) {
            int row = m0 + wm + mt * 16 + (lane >> 2);
            float2 v0 = {acc[mt][nt][0] + b0, acc[mt][nt][1] + b1};
            float2 v1 = {acc[mt][nt][2] + b0, acc[mt][nt][3] + b1};
            *(float2*)(C + (size_t)row * N + col) = v0;
            *(float2*)(C + (size_t)(row + 8) * N + col) = v1;
        }
    }
}

// ---------------------------------------------------------------------------
// Fused RMSNorm + RoPE -> split-bf16 output
// ---------------------------------------------------------------------------
__global__ __launch_bounds__(256) void rmsrope_split_kernel(
    const float* __restrict__ t, const float* __restrict__ cosT,
    const float* __restrict__ sinT, const float* __restrict__ scale, int heads,
    __nv_bfloat16* __restrict__ oh, __nv_bfloat16* __restrict__ ol)
{
    int gw   = (blockIdx.x * 256 + threadIdx.x) >> 5;
    int lane = threadIdx.x & 31;
    if (gw >= NTOK * heads) return;
    int token = gw / heads;
    int h     = gw - token * heads;
    int s     = token & (S_ - 1);

    const float* row = t + ((size_t)token * heads + h) * D_;
    float4 x = *(const float4*)(row + lane * 4);

    float ss = fmaf(x.x, x.x, fmaf(x.y, x.y, fmaf(x.z, x.z, x.w * x.w)));
#pragma unroll
    for (int o = 16; o; o >>= 1) ss += __shfl_xor_sync(0xffffffffu, ss, o);
    float r = rsqrtf(ss * (1.0f / D_) + 1e-6f);

    float4 sc = *(const float4*)(scale + lane * 4);
    float4 y;
    y.x = x.x * r * sc.x; y.y = x.y * r * sc.y;
    y.z = x.z * r * sc.z; y.w = x.w * r * sc.w;

    float4 p;
    p.x = __shfl_xor_sync(0xffffffffu, y.x, 16);
    p.y = __shfl_xor_sync(0xffffffffu, y.y, 16);
    p.z = __shfl_xor_sync(0xffffffffu, y.z, 16);
    p.w = __shfl_xor_sync(0xffffffffu, y.w, 16);

    float4 c  = *(const float4*)(cosT + (size_t)s * D_ + lane * 4);
    float4 sn = *(const float4*)(sinT + (size_t)s * D_ + lane * 4);
    float sg  = (lane < 16) ? -1.f : 1.f;

    float o0 = fmaf(y.x, c.x, sg * p.x * sn.x);
    float o1 = fmaf(y.y, c.y, sg * p.y * sn.y);
    float o2 = fmaf(y.z, c.z, sg * p.z * sn.z);
    float o3 = fmaf(y.w, c.w, sg * p.w * sn.w);

    size_t off = ((size_t)token * heads + h) * D_ + lane * 4;
    __nv_bfloat16 h0 = __float2bfloat16(o0), h1 = __float2bfloat16(o1);
    __nv_bfloat16 h2 = __float2bfloat16(o2), h3 = __float2bfloat16(o3);
    *(__nv_bfloat162*)(oh + off)     = __nv_bfloat162(h0, h1);
    *(__nv_bfloat162*)(oh + off + 2) = __nv_bfloat162(h2, h3);
    *(__nv_bfloat162*)(ol + off) =
        __nv_bfloat162(__float2bfloat16(o0 - __bfloat162float(h0)),
                       __float2bfloat16(o1 - __bfloat162float(h1)));
    *(__nv_bfloat162*)(ol + off + 2) =
        __nv_bfloat162(__float2bfloat16(o2 - __bfloat162float(h2)),
                       __float2bfloat16(o3 - __bfloat162float(h3)));
}

// ---------------------------------------------------------------------------
// Flash attention, HMMA bf16 3-term split, causal, GQA.
// 64 q-rows/block, k-tiles of 64, 8 warps = 4(m16) x 2(col-half).
// ---------------------------------------------------------------------------
#define QK_STRIDE 272                 // 128 bf16 + 16B pad
#define P_STRIDE  144                 // 64 bf16 + 16B pad
#define ASM_QH  0
#define ASM_QL  (ASM_QH + 64 * QK_STRIDE)
#define ASM_KH  (ASM_QL + 64 * QK_STRIDE)
#define ASM_KL  (ASM_KH + 64 * QK_STRIDE)
#define ASM_VH  (ASM_KL + 64 * QK_STRIDE)
#define ASM_VL  (ASM_VH + 64 * QK_STRIDE)
#define ASM_PH  (ASM_VL + 64 * QK_STRIDE)
#define ASM_PL  (ASM_PH + 64 * P_STRIDE)
#define ASM_S   (ASM_PL + 64 * P_STRIDE)      // fp32, stride 66 floats
#define ASM_M   (ASM_S + 64 * 66 * 4)
#define ASM_L   (ASM_M + 256)
#define ASM_F   (ASM_L + 256)
#define ASM_TOTAL (ASM_F + 256)               // 140,544 B

__global__ __launch_bounds__(256, 1) void attn_hmma_kernel(
    const __nv_bfloat16* __restrict__ qh, const __nv_bfloat16* __restrict__ ql,
    const __nv_bfloat16* __restrict__ kh, const __nv_bfloat16* __restrict__ kl,
    const __nv_bfloat16* __restrict__ vh, const __nv_bfloat16* __restrict__ vl,
    float* __restrict__ ctx)
{
    extern __shared__ char smem[];
    const uint32_t sbase = smem_u32(smem);
    float* sS = (float*)(smem + ASM_S);
    float* sM = (float*)(smem + ASM_M);
    float* sL = (float*)(smem + ASM_L);
    float* sF = (float*)(smem + ASM_F);

    const int tid = threadIdx.x, wid = tid >> 5, lane = tid & 31;
    const int qt = blockIdx.x, h = blockIdx.y, b = blockIdx.z;
    const int kvh  = h >> 2;
    const int tok0 = b * S_ + qt * 64;

    const int mr = wid & 3;     // m16 tile index (q rows mr*16..)
    const int nc = wid >> 2;    // 0/1: col-half

    // Load Q tiles (64 rows x 128 bf16, h & l)
    for (int i = tid; i < 64 * 16; i += 256) {
        int r = i >> 4, c = i & 15;
        size_t g = (size_t)(tok0 + r) * HD_ + h * D_ + c * 8;
        *(uint4*)(smem + ASM_QH + r * QK_STRIDE + c * 16) = *(const uint4*)(qh + g);
        *(uint4*)(smem + ASM_QL + r * QK_STRIDE + c * 16) = *(const uint4*)(ql + g);
    }
    if (tid < 64) { sM[tid] = -FLT_MAX; sL[tid] = 0.f; }

    float ctxacc[8][4];
#pragma unroll
    for (int i = 0; i < 8; i++)
#pragma unroll
        for (int f = 0; f < 4; f++) ctxacc[i][f] = 0.f;

    // fragment lane addressing (validated in GEMM)
    const int a_row = (lane & 7) + ((lane >> 3) & 1) * 8;
    const int a_kB  = (lane >> 4) * 16;
    const int seg   = lane >> 3;
    const int b_row = (lane & 7) + (seg >> 1) * 8;
    const int b_kB  = (seg & 1) * 16;
    // trans B-side (for V: [j][d] row-major -> B frags): row = k(j), col-byte = d
    const int t_row = (lane & 7) + (seg & 1) * 8;
    const int t_cB  = (seg >> 1) * 16;

    const float rsc = 0.08838834764831845f;  // 1/sqrt(128)
    const int row_a = mr * 16 + (lane >> 2); // frag row (and +8)

    for (int kt = 0; kt <= qt; kt++) {
        const int ktok0 = b * S_ + kt * 64;
        __syncthreads();
        // load K and V tiles (h & l), row-major [token][d]
        for (int i = tid; i < 64 * 16; i += 256) {
            int r = i >> 4, c = i & 15;
            size_t g = (size_t)(ktok0 + r) * KVD_ + kvh * D_ + c * 8;
            *(uint4*)(smem + ASM_KH + r * QK_STRIDE + c * 16) = *(const uint4*)(kh + g);
            *(uint4*)(smem + ASM_KL + r * QK_STRIDE + c * 16) = *(const uint4*)(kl + g);
            *(uint4*)(smem + ASM_VH + r * QK_STRIDE + c * 16) = *(const uint4*)(vh + g);
            *(uint4*)(smem + ASM_VL + r * QK_STRIDE + c * 16) = *(const uint4*)(vl + g);
        }
        __syncthreads();

        // ---- QK^T: S(16 x 32 per warp) = Qh*Kh + Qh*Kl + Ql*Kh ----
        float sacc[4][4];
#pragma unroll
        for (int i = 0; i < 4; i++)
#pragma unroll
            for (int f = 0; f < 4; f++) sacc[i][f] = 0.f;

#pragma unroll
        for (int ks = 0; ks < 8; ks++) {
            const int kB = ks * 32;
            uint32_t ah[4], al[4];
            ldsm4(ah[0], ah[1], ah[2], ah[3],
                  sbase + ASM_QH + (mr * 16 + a_row) * QK_STRIDE + kB + a_kB);
            ldsm4(al[0], al[1], al[2], al[3],
                  sbase + ASM_QL + (mr * 16 + a_row) * QK_STRIDE + kB + a_kB);
#pragma unroll
            for (int bt = 0; bt < 2; bt++) {
                uint32_t r0, r1, r2, r3;
                ldsm4(r0, r1, r2, r3,
                      sbase + ASM_KH + (nc * 32 + bt * 16 + b_row) * QK_STRIDE + kB + b_kB);
                mma_bf16(sacc[bt * 2],     ah[0], ah[1], ah[2], ah[3], r0, r1);
                mma_bf16(sacc[bt * 2 + 1], ah[0], ah[1], ah[2], ah[3], r2, r3);
                mma_bf16(sacc[bt * 2],     al[0], al[1], al[2], al[3], r0, r1);
                mma_bf16(sacc[bt * 2 + 1], al[0], al[1], al[2], al[3], r2, r3);
                uint32_t s0, s1, s2, s3;
                ldsm4(s0, s1, s2, s3,
                      sbase + ASM_KL + (nc * 32 + bt * 16 + b_row) * QK_STRIDE + kB + b_kB);
                mma_bf16(sacc[bt * 2],     ah[0], ah[1], ah[2], ah[3], s0, s1);
                mma_bf16(sacc[bt * 2 + 1], ah[0], ah[1], ah[2], ah[3], s2, s3);
            }
        }
        // write S frags (scaled) to smem
#pragma unroll
        for (int nt = 0; nt < 4; nt++) {
            int col = nc * 32 + nt * 8 + (lane & 3) * 2;
            *(float2*)&sS[row_a * 66 + col] =
                make_float2(sacc[nt][0] * rsc, sacc[nt][1] * rsc);
            *(float2*)&sS[(row_a + 8) * 66 + col] =
                make_float2(sacc[nt][2] * rsc, sacc[nt][3] * rsc);
        }
        __syncthreads();

        // ---- online softmax: row r = tid>>2, quad lane q4 = tid&3 (16 cols) ----
        {
            const int r = tid >> 2, q4 = tid & 3;
            const int j0 = q4 * 16;
            const bool diag = (kt == qt);
            float mold = sM[r];
            float sv[16];
            float tm = -FLT_MAX;
#pragma unroll
            for (int jj = 0; jj < 16; jj++) {
                float v = sS[r * 66 + j0 + jj];
                if (diag && (j0 + jj) > r) v = -FLT_MAX;
                sv[jj] = v;
                tm = fmaxf(tm, v);
            }
            tm = fmaxf(tm, __shfl_xor_sync(0xffffffffu, tm, 1));
            tm = fmaxf(tm, __shfl_xor_sync(0xffffffffu, tm, 2));
            tm = fmaxf(tm, mold);
            float ps = 0.f;
            __nv_bfloat16* ph = (__nv_bfloat16*)(smem + ASM_PH + r * P_STRIDE) + j0;
            __nv_bfloat16* pl = (__nv_bfloat16*)(smem + ASM_PL + r * P_STRIDE) + j0;
#pragma unroll
            for (int jj = 0; jj < 16; jj++) {
                float p = __expf(sv[jj] - tm);
                ps += p;
                __nv_bfloat16 hh = __float2bfloat16(p);
                ph[jj] = hh;
                pl[jj] = __float2bfloat16(p - __bfloat162float(hh));
            }
            ps += __shfl_xor_sync(0xffffffffu, ps, 1);
            ps += __shfl_xor_sync(0xffffffffu, ps, 2);
            if (q4 == 0) {
                float fsc = __expf(mold - tm);
                sM[r] = tm;
                sL[r] = sL[r] * fsc + ps;
                sF[r] = fsc;
            }
        }
        __syncthreads();

        // ---- rescale ctx accs, then PV: ctx += Ph*V + (PhVl + PlVh) ----
        {
            float f0 = sF[row_a], f1 = sF[row_a + 8];
#pragma unroll
            for (int nt = 0; nt < 8; nt++) {
                ctxacc[nt][0] *= f0; ctxacc[nt][1] *= f0;
                ctxacc[nt][2] *= f1; ctxacc[nt][3] *= f1;
            }
        }
#pragma unroll
        for (int ks = 0; ks < 4; ks++) {
            const int kB = ks * 32;        // 16 tokens * 2B
            uint32_t ph4[4], pl4[4];
            ldsm4(ph4[0], ph4[1], ph4[2], ph4[3],
                  sbase + ASM_PH + (mr * 16 + a_row) * P_STRIDE + kB + a_kB);
            ldsm4(pl4[0], pl4[1], pl4[2], pl4[3],
                  sbase + ASM_PL + (mr * 16 + a_row) * P_STRIDE + kB + a_kB);
#pragma unroll
            for (int bt = 0; bt < 4; bt++) {
                // trans-load of V[j][d]: rows = token (k), 16 d cols
                uint32_t r0, r1, r2, r3;
                ldsm4t(r0, r1, r2, r3,
                       sbase + ASM_VH + (ks * 16 + t_row) * QK_STRIDE
                             + nc * 128 + bt * 32 + t_cB);
                mma_bf16(ctxacc[bt * 2],     ph4[0], ph4[1], ph4[2], ph4[3], r0, r1);
                mma_bf16(ctxacc[bt * 2 + 1], ph4[0], ph4[1], ph4[2], ph4[3], r2, r3);
                mma_bf16(ctxacc[bt * 2],     pl4[0], pl4[1], pl4[2], pl4[3], r0, r1);
                mma_bf16(ctxacc[bt * 2 + 1], pl4[0], pl4[1], pl4[2], pl4[3], r2, r3);
                uint32_t s0, s1, s2, s3;
                ldsm4t(s0, s1, s2, s3,
                       sbase + ASM_VL + (ks * 16 + t_row) * QK_STRIDE
                             + nc * 128 + bt * 32 + t_cB);
                mma_bf16(ctxacc[bt * 2],     ph4[0], ph4[1], ph4[2], ph4[3], s0, s1);
                mma_bf16(ctxacc[bt * 2 + 1], ph4[0], ph4[1], ph4[2], ph4[3], s2, s3);
            }
        }
    }

    __syncthreads();
    const float inv0 = 1.0f / sL[row_a];
    const float inv1 = 1.0f / sL[row_a + 8];
#pragma unroll
    for (int nt = 0; nt < 8; nt++) {
        int col = nc * 64 + nt * 8 + (lane & 3) * 2;
        float* p0 = ctx + (size_t)(tok0 + row_a) * HD_ + h * D_ + col;
        float* p1 = ctx + (size_t)(tok0 + row_a + 8) * HD_ + h * D_ + col;
        *(float2*)p0 = make_float2(ctxacc[nt][0] * inv0, ctxacc[nt][1] * inv0);
        *(float2*)p1 = make_float2(ctxacc[nt][2] * inv1, ctxacc[nt][3] * inv1);
    }
}

// ---------------------------------------------------------------------------
// Inputs: 0:x 1:mask 2:cos 3:sin 4:Wq 5:bq 6:Wk 7:bk 8:Wv 9:bv 10:Wo 11:qs 12:ks
// ---------------------------------------------------------------------------
extern "C" void kernel_launch(void* const* d_in, const int* in_sizes, int n_in,
                              void* d_out, int out_size)
{
    const float* x    = (const float*)d_in[0];
    const float* cosT = (const float*)d_in[2];
    const float* sinT = (const float*)d_in[3];
    const float* Wq   = (const float*)d_in[4];
    const float* bq   = (const float*)d_in[5];
    const float* Wk   = (const float*)d_in[6];
    const float* bk   = (const float*)d_in[7];
    const float* Wv   = (const float*)d_in[8];
    const float* bv   = (const float*)d_in[9];
    const float* Wo   = (const float*)d_in[10];
    const float* qs   = (const float*)d_in[11];
    const float* ks   = (const float*)d_in[12];
    float* out = (float*)d_out;
    (void)in_sizes; (void)n_in; (void)out_size;

    float *dq, *dk, *dv, *dctx;
    cudaGetSymbolAddress((void**)&dq, g_q);
    cudaGetSymbolAddress((void**)&dk, g_k);
    cudaGetSymbolAddress((void**)&dv, g_v);
    cudaGetSymbolAddress((void**)&dctx, g_ctx);
    __nv_bfloat16 *xh, *xl, *ch, *cl, *wqh, *wql, *wkh, *wkl, *wvh, *wvl, *woh, *wol;
    __nv_bfloat16 *aqh, *aql, *akh, *akl, *avh, *avl;
    cudaGetSymbolAddress((void**)&xh, g_xh);   cudaGetSymbolAddress((void**)&xl, g_xl);
    cudaGetSymbolAddress((void**)&ch, g_ch);   cudaGetSymbolAddress((void**)&cl, g_cl);
    cudaGetSymbolAddress((void**)&wqh, g_wqh); cudaGetSymbolAddress((void**)&wql, g_wql);
    cudaGetSymbolAddress((void**)&wkh, g_wkh); cudaGetSymbolAddress((void**)&wkl, g_wkl);
    cudaGetSymbolAddress((void**)&wvh, g_wvh); cudaGetSymbolAddress((void**)&wvl, g_wvl);
    cudaGetSymbolAddress((void**)&woh, g_woh); cudaGetSymbolAddress((void**)&wol, g_wol);
    cudaGetSymbolAddress((void**)&aqh, g_qh);  cudaGetSymbolAddress((void**)&aql, g_ql);
    cudaGetSymbolAddress((void**)&akh, g_kh);  cudaGetSymbolAddress((void**)&akl, g_kl);
    cudaGetSymbolAddress((void**)&avh, g_vh);  cudaGetSymbolAddress((void**)&avl, g_vl);

    cudaFuncSetAttribute(attn_hmma_kernel, cudaFuncAttributeMaxDynamicSharedMemorySize,
                         ASM_TOTAL);
    cudaFuncSetAttribute(gemm_hmma_kernel, cudaFuncAttributeMaxDynamicSharedMemorySize,
                         GSM_TOTAL);

    dim3 t256(256);
    dim3 t32x8(32, 8);

    split_kernel<<<(NTOK * E_) / 256, t256>>>(x, xh, xl, NTOK * E_);
    transpose_split_kernel<<<dim3(HD_ / 32, E_ / 32), t32x8>>>(Wq, wqh, wql, E_, HD_);
    transpose_split_kernel<<<dim3(KVD_ / 32, E_ / 32), t32x8>>>(Wk, wkh, wkl, E_, KVD_);
    transpose_split_kernel<<<dim3(KVD_ / 32, E_ / 32), t32x8>>>(Wv, wvh, wvl, E_, KVD_);
    transpose_split_kernel<<<dim3(E_ / 32, HD_ / 32), t32x8>>>(Wo, woh, wol, HD_, E_);

    gemm_hmma_kernel<<<dim3(HD_ / 128, NTOK / 128), t256, GSM_TOTAL>>>(
        xh, xl, wqh, wql, bq, dq, NTOK, HD_, E_);
    gemm_hmma_kernel<<<dim3(KVD_ / 128, NTOK / 128), t256, GSM_TOTAL>>>(
        xh, xl, wkh, wkl, bk, dk, NTOK, KVD_, E_);
    gemm_hmma_kernel<<<dim3(KVD_ / 128, NTOK / 128), t256, GSM_TOTAL>>>(
        xh, xl, wvh, wvl, bv, dv, NTOK, KVD_, E_);

    rmsrope_split_kernel<<<(NTOK * H_ * 32) / 256, t256>>>(dq, cosT, sinT, qs, H_, aqh, aql);
    rmsrope_split_kernel<<<(NTOK * KV_ * 32) / 256, t256>>>(dk, cosT, sinT, ks, KV_, akh, akl);
    split_kernel<<<(NTOK * KVD_) / 256, t256>>>(dv, avh, avl, NTOK * KVD_);

    attn_hmma_kernel<<<dim3(S_ / 64, H_, B_), t256, ASM_TOTAL>>>(
        aqh, aql, akh, akl, avh, avl, dctx);

    split_kernel<<<(NTOK * HD_) / 256, t256>>>(dctx, ch, cl, NTOK * HD_);
    gemm_hmma_kernel<<<dim3(E_ / 128, NTOK / 128), t256, GSM_TOTAL>>>(
        ch, cl, woh, wol, nullptr, out, NTOK, E_, HD_);
}